// round 13
// baseline (speedup 1.0000x reference)
#include <cuda_runtime.h>
#include <float.h>
#include <stdint.h>

#define DIM 128
#define N_SAMPLES 8192
#define N_EMBED 10000
#define N_EMBED_PAD 10240
#define TM 64
#define TN 64
#define THREADS 256
#define NSLICE 16
#define SLICE_W 640
#define NCH 10

typedef unsigned long long u64;

__device__ float    g_cnorm[N_EMBED_PAD];
__device__ u64      g_best[N_SAMPLES];
__device__ __align__(256) uint32_t g_bT[N_EMBED_PAD * (DIM / 2)];  // fp16 [n][k] word-packed
__device__ u64      g_t1[NSLICE * N_SAMPLES];
__device__ float    g_t2[NSLICE * N_SAMPLES];
__device__ float    g_eps[N_SAMPLES];
__device__ unsigned g_maxbhi, g_maxblo;
__device__ int      g_rescue_count;
__device__ int      g_rescue_list[N_SAMPLES];

__device__ __forceinline__ unsigned smem_u32(const void* p) {
    return (unsigned)__cvta_generic_to_shared(p);
}
__device__ __forceinline__ void cp16(unsigned dst, const void* src) {
    asm volatile("cp.async.cg.shared.global [%0], [%1], 16;" :: "r"(dst), "l"(src));
}
__device__ __forceinline__ void cp16z(unsigned dst, const void* src, int sz) {
    asm volatile("cp.async.cg.shared.global [%0], [%1], 16, %2;"
                 :: "r"(dst), "l"(src), "r"(sz));
}
__device__ __forceinline__ u64 enc_best(float v, int j) {
    unsigned b = __float_as_uint(v);
    b = ((int)b < 0) ? ~b : (b | 0x80000000u);
    return ((u64)b << 32) | (unsigned)(~j);
}
__device__ __forceinline__ float dec_val(u64 p) {
    unsigned b = (unsigned)(p >> 32);
    unsigned f = (b & 0x80000000u) ? (b ^ 0x80000000u) : ~b;
    return __uint_as_float(f);
}
__device__ __forceinline__ float f16rt(float v, float* lo) {
    unsigned short hb; float hf;
    asm("cvt.rn.f16.f32 %0, %1;" : "=h"(hb) : "f"(v));
    asm("cvt.f32.f16 %0, %1;"    : "=f"(hf) : "h"(hb));
    *lo = v - hf;
    return hf;
}
__device__ __forceinline__ unsigned short f16of(float v) {
    unsigned short hb;
    asm("cvt.rn.f16.f32 %0, %1;" : "=h"(hb) : "f"(v));
    return hb;
}
__device__ __forceinline__ void hsplit2hi(float x, float y, uint32_t& hw) {
    hw = (uint32_t)f16of(x) | ((uint32_t)f16of(y) << 16);
}
__device__ __forceinline__ void mma_f16(float* d, uint4 a, uint32_t b0, uint32_t b1) {
    asm volatile(
        "mma.sync.aligned.m16n8k16.row.col.f32.f16.f16.f32 "
        "{%0,%1,%2,%3}, {%4,%5,%6,%7}, {%8,%9}, {%0,%1,%2,%3};"
        : "+f"(d[0]), "+f"(d[1]), "+f"(d[2]), "+f"(d[3])
        : "r"(a.x), "r"(a.y), "r"(a.z), "r"(a.w), "r"(b0), "r"(b1));
}
__device__ __forceinline__ void ldmx4(uint32_t& r0, uint32_t& r1, uint32_t& r2,
                                      uint32_t& r3, unsigned addr) {
    asm volatile("ldmatrix.sync.aligned.m8n8.x4.shared.b16 {%0,%1,%2,%3}, [%4];"
                 : "=r"(r0), "=r"(r1), "=r"(r2), "=r"(r3) : "r"(addr));
}

// ---------------- prep: cnorm + b-split norm maxes + counter reset ----------------
__global__ void cnorm_kernel(const float* __restrict__ cm) {
    __shared__ float red[3][4][64];
    __shared__ unsigned mhi, mlo;
    const int tid = threadIdx.x;
    const int jl  = tid & 63;
    const int dc  = tid >> 6;
    const int j   = blockIdx.x * 64 + jl;
    if (tid == 0) { mhi = 0; mlo = 0; }
    if (blockIdx.x == 0 && tid == 0) g_rescue_count = 0;
    __syncthreads();
    float s_cn = 0.f, s_hi = 0.f, s_lo = 0.f;
    if (j < N_EMBED) {
#pragma unroll 8
        for (int dd = 0; dd < 32; dd++) {
            float v = cm[(dc * 32 + dd) * N_EMBED + j];
            float lo, hf = f16rt(v, &lo);
            s_cn += v * v; s_hi += hf * hf; s_lo += lo * lo;
        }
    }
    red[0][dc][jl] = s_cn; red[1][dc][jl] = s_hi; red[2][dc][jl] = s_lo;
    __syncthreads();
    if (dc == 0) {
        float cn = red[0][0][jl] + red[0][1][jl] + red[0][2][jl] + red[0][3][jl];
        float hi = red[1][0][jl] + red[1][1][jl] + red[1][2][jl] + red[1][3][jl];
        float lo = red[2][0][jl] + red[2][1][jl] + red[2][2][jl] + red[2][3][jl];
        g_cnorm[j] = (j < N_EMBED) ? cn : -1e30f;
        if (j < N_EMBED) {
            atomicMax(&mhi, __float_as_uint(hi));
            atomicMax(&mlo, __float_as_uint(lo));
        }
    }
    __syncthreads();
    if (tid == 0) {
        atomicMax(&g_maxbhi, mhi);
        atomicMax(&g_maxblo, mlo);
    }
}

// Transpose cluster_mean [k][j] fp32 -> g_bT [j][k] fp16 word-packed (zero pad).
__global__ void prep_b_kernel(const float* __restrict__ cm) {
    __shared__ unsigned short t[32][34];
    const int jt = blockIdx.x, kt = blockIdx.y;
    const int tx = threadIdx.x, ty = threadIdx.y;   // (32, 8)
#pragma unroll
    for (int r = 0; r < 4; r++) {
        int k = kt * 32 + ty + r * 8;
        int j = jt * 32 + tx;
        float v = (j < N_EMBED) ? cm[k * N_EMBED + j] : 0.f;
        t[ty + r * 8][tx] = f16of(v);
    }
    __syncthreads();
    const int tid = ty * 32 + tx;
#pragma unroll
    for (int r = 0; r < 2; r++) {
        int i  = tid + r * 256;
        int jl = i >> 4;
        int w  = i & 15;
        uint32_t word = (uint32_t)t[2 * w][jl] | ((uint32_t)t[2 * w + 1][jl] << 16);
        g_bT[(size_t)(jt * 32 + jl) * (DIM / 2) + kt * 16 + w] = word;
    }
}

// Per-sample sound error bound.
__global__ void prep_aeps_kernel(const float* __restrict__ A) {
    const int w = threadIdx.x >> 5, lane = threadIdx.x & 31;
    const int s = blockIdx.x * 8 + w;
    float shi = 0.f, slo = 0.f;
#pragma unroll
    for (int r = 0; r < 4; r++) {
        float a = -2.f * A[s * DIM + lane + 32 * r];
        float lo, hf = f16rt(a, &lo);
        shi += hf * hf; slo += lo * lo;
    }
#pragma unroll
    for (int off = 16; off > 0; off >>= 1) {
        shi += __shfl_xor_sync(0xFFFFFFFFu, shi, off);
        slo += __shfl_xor_sync(0xFFFFFFFFu, slo, off);
    }
    if (lane == 0) {
        float MBHI = sqrtf(__uint_as_float(g_maxbhi));
        float MBLO = sqrtf(__uint_as_float(g_maxblo));
        float nlo = sqrtf(slo), nhi = sqrtf(shi);
        g_eps[s] = 2.0002f * (nlo * MBHI + nhi * MBLO + nlo * MBLO) + 0.02f;
    }
}

// ---------------- phase1: hi-only mma, A in registers, per-slice top-2 --------
#define AW     4096
#define BROW   68                        // words per n-row (272B: conflict-free ldmatrix)
#define BHALF  (TN * BROW)
#define SMEM_WORDS (AW + 2 * BHALF + 768)

__global__ __launch_bounds__(THREADS, 2)
void phase1_kernel(const float* __restrict__ A) {
    extern __shared__ uint32_t smw[];
    uint32_t* Aw = smw;
    uint32_t* Bw = smw + AW;
    u64*   mt1 = (u64*)(smw + AW + 2 * BHALF);
    float* mt2 = (float*)(smw + AW + 2 * BHALF + 512);

    const int tid  = threadIdx.x;
    const int lane = tid & 31;
    const int sy   = tid >> 5;
    const int wm   = sy >> 2;
    const int wn   = sy & 3;
    const int n0w  = wn * 16;
    const int mtg0 = wm * 2;
    const int tig  = lane & 3;

    const int mt  = blockIdx.x & 127;
    const int sl  = blockIdx.x >> 7;
    const int m0  = mt * TM;
    const int j00 = sl * SLICE_W;

    // ldmatrix row address for this lane
    const int lm  = lane >> 3, lr = lane & 7;
    const int lrow = n0w + ((lm >> 1) & 1) * 8 + lr;
    const int lkb  = (lm & 1) * 8;
    const unsigned bbase = smem_u32(Bw) + lrow * (BROW * 4) + lkb * 2;

    auto issueB = [&](int t) {
        const int j0 = j00 + t * TN;
        uint32_t* dst = Bw + (t & 1) * BHALF;
        for (int i = tid; i < 1024; i += THREADS) {
            int r = i >> 4, s = i & 15;
            cp16(smem_u32(dst + r * BROW + s * 4),
                 g_bT + (size_t)(j0 + r) * (DIM / 2) + s * 4);
        }
        asm volatile("cp.async.commit_group;");
    };

    issueB(0);
    issueB(1);

    // A hi split into smem staging (fragment-major), then hoist to registers.
    for (int i = tid; i < 1024; i += THREADS) {
        int li = i & 31;
        int ks = (i >> 5) & 7;
        int mq = i >> 8;
        int r = li >> 2, tg = li & 3;
        int row0 = m0 + mq * 16 + r;
        int c0 = ks * 16 + 2 * tg;
        const float* A0 = A + (size_t)row0 * DIM;
        const float* A1 = A0 + 8 * DIM;
        uint32_t h0, h1, h2, h3;
        hsplit2hi(-2.f * A0[c0],     -2.f * A0[c0 + 1], h0);
        hsplit2hi(-2.f * A1[c0],     -2.f * A1[c0 + 1], h1);
        hsplit2hi(-2.f * A0[c0 + 8], -2.f * A0[c0 + 9], h2);
        hsplit2hi(-2.f * A1[c0 + 8], -2.f * A1[c0 + 9], h3);
        *(uint4*)&Aw[((mq * 8 + ks) * 32 + li) * 4] = make_uint4(h0, h1, h2, h3);
    }
    __syncthreads();

    // A fragments live in registers for the whole kernel (no per-chunk reload).
    uint4 ah[2][8];
#pragma unroll
    for (int mq = 0; mq < 2; mq++)
#pragma unroll
        for (int ks = 0; ks < 8; ks++)
            ah[mq][ks] = *(const uint4*)&Aw[(((mtg0 + mq) * 8 + ks) * 32 + lane) * 4];

    float b1[4], b2[4];
    int   j1[4];
#pragma unroll
    for (int i = 0; i < 4; i++) { b1[i] = -FLT_MAX; b2[i] = -FLT_MAX; j1[i] = 0; }

    for (int t = 0; t < NCH; t++) {
        if (t < NCH - 1) asm volatile("cp.async.wait_group 1;");
        else             asm volatile("cp.async.wait_group 0;");
        __syncthreads();

        const unsigned baddr0 = bbase + (t & 1) * (BHALF * 4);
        const int j0 = j00 + t * TN;

        float acc[2][2][4];
#pragma unroll
        for (int nt = 0; nt < 2; nt++) {
            int c0 = j0 + n0w + nt * 8 + 2 * tig;
            float cn0 = __ldg(&g_cnorm[c0]);
            float cn1 = __ldg(&g_cnorm[c0 + 1]);
#pragma unroll
            for (int mq = 0; mq < 2; mq++) {
                acc[mq][nt][0] = cn0; acc[mq][nt][1] = cn1;
                acc[mq][nt][2] = cn0; acc[mq][nt][3] = cn1;
            }
        }

#pragma unroll
        for (int ks = 0; ks < 8; ks++) {
            uint32_t bb0, bb1, bb2, bb3;
            ldmx4(bb0, bb1, bb2, bb3, baddr0 + ks * 32);
            mma_f16(acc[0][0], ah[0][ks], bb0, bb1);
            mma_f16(acc[1][0], ah[1][ks], bb0, bb1);
            mma_f16(acc[0][1], ah[0][ks], bb2, bb3);
            mma_f16(acc[1][1], ah[1][ks], bb2, bb3);
        }

        // top-2 update (ascending j preserves first-occurrence for top1).
#pragma unroll
        for (int nt = 0; nt < 2; nt++) {
            int c0 = j0 + n0w + nt * 8 + 2 * tig;
#pragma unroll
            for (int mq = 0; mq < 2; mq++) {
#pragma unroll
                for (int rb = 0; rb < 2; rb++) {
                    int st = mq * 2 + rb;
                    float v0 = acc[mq][nt][rb * 2 + 0];
                    float v1 = acc[mq][nt][rb * 2 + 1];
                    if (v0 > b1[st]) { b2[st] = b1[st]; b1[st] = v0; j1[st] = c0; }
                    else if (v0 > b2[st]) b2[st] = v0;
                    if (v1 > b1[st]) { b2[st] = b1[st]; b1[st] = v1; j1[st] = c0 + 1; }
                    else if (v1 > b2[st]) b2[st] = v1;
                }
            }
        }

        __syncthreads();
        if (t + 2 < NCH) issueB(t + 2);
    }

    // quad merge, stash per-wn, cross-warp merge.
#pragma unroll
    for (int s = 0; s < 4; s++) {
        float v = b1[s], v2 = b2[s];
        int   bj = j1[s];
#pragma unroll
        for (int off = 1; off < 4; off <<= 1) {
            float ov  = __shfl_xor_sync(0xFFFFFFFFu, v, off);
            int   oj  = __shfl_xor_sync(0xFFFFFFFFu, bj, off);
            float ov2 = __shfl_xor_sync(0xFFFFFFFFu, v2, off);
            float nv2 = fmaxf(fmaxf(v2, ov2), fminf(v, ov));
            if (ov > v || (ov == v && oj < bj)) { v = ov; bj = oj; }
            v2 = nv2;
        }
        if ((lane & 3) == 0) {
            int mq = s >> 1, rb = s & 1;
            int rl = (mtg0 + mq) * 16 + (lane >> 2) + rb * 8;
            mt1[wn * 64 + rl] = enc_best(v, bj);
            mt2[wn * 64 + rl] = v2;
        }
    }
    __syncthreads();
    if (tid < 64) {
        int r = tid;
        u64 m = mt1[r]; int wi = 0;
        for (int w = 1; w < 4; w++) {
            u64 t = mt1[w * 64 + r];
            if (t > m) { m = t; wi = w; }
        }
        float v2 = -FLT_MAX;
        for (int w = 0; w < 4; w++) {
            float c = (w == wi) ? mt2[w * 64 + r]
                                : fmaxf(dec_val(mt1[w * 64 + r]), mt2[w * 64 + r]);
            v2 = fmaxf(v2, c);
        }
        g_t1[sl * N_SAMPLES + m0 + r] = m;
        g_t2[sl * N_SAMPLES + m0 + r] = v2;
    }
}

// ---------------- combine: global top-2, gap test, rescue list ----------------
__global__ void combine_kernel() {
    const int s = blockIdx.x * 256 + threadIdx.x;
    u64 m1 = 0; int i1 = 0;
#pragma unroll
    for (int i = 0; i < NSLICE; i++) {
        u64 t = g_t1[i * N_SAMPLES + s];
        if (t > m1) { m1 = t; i1 = i; }
    }
    float v1 = dec_val(m1);
    float v2 = -FLT_MAX;
#pragma unroll
    for (int i = 0; i < NSLICE; i++) {
        float c = (i == i1) ? g_t2[i * N_SAMPLES + s]
                            : fmaxf(dec_val(g_t1[i * N_SAMPLES + s]),
                                    g_t2[i * N_SAMPLES + s]);
        v2 = fmaxf(v2, c);
    }
    if (v1 - v2 > g_eps[s]) {
        g_best[s] = m1;
    } else {
        g_best[s] = 0;
        int p = atomicAdd(&g_rescue_count, 1);
        g_rescue_list[p] = s;
    }
}

// ---------------- rescue: exact fp32 re-scan for contested samples ----------------
#define RS_AW 4096
#define RS_BW 16384
__global__ __launch_bounds__(256)
void rescue_kernel(const float* __restrict__ A, const float* __restrict__ Bm) {
    const int cnt = *(volatile int*)&g_rescue_count;
    const int sb = blockIdx.x >> 3, sl = blockIdx.x & 7;
    if (sb * 32 >= cnt) return;
    const int nval = min(32, cnt - sb * 32);

    extern __shared__ float smf[];
    float* As = smf;
    float* Bs = smf + RS_AW;

    const int tid = threadIdx.x, lane = tid & 31, w = tid >> 5;
    const int j00 = sl * 1280;

    auto issueB = [&](int t) {
        const int j0 = j00 + t * 128;
        float* dst = Bs + (t & 1) * RS_BW;
        for (int i = tid; i < 4096; i += 256) {
            int k = i >> 5, j4 = (i & 31) * 4;
            int j = j0 + j4;
            cp16z(smem_u32(dst + k * 128 + j4),
                  Bm + (size_t)k * N_EMBED + min(j, N_EMBED - 4),
                  (j < N_EMBED) ? 16 : 0);
        }
        asm volatile("cp.async.commit_group;");
    };

    issueB(0);
    issueB(1);

    for (int i = tid; i < 1024; i += 256) {
        int si = i >> 5, k4 = (i & 31) * 4;
        float4 v = make_float4(0.f, 0.f, 0.f, 0.f);
        if (si < nval) {
            int s = g_rescue_list[sb * 32 + si];
            v = *(const float4*)&A[(size_t)s * DIM + k4];
        }
        As[(k4 + 0) * 32 + si] = -2.f * v.x;
        As[(k4 + 1) * 32 + si] = -2.f * v.y;
        As[(k4 + 2) * 32 + si] = -2.f * v.z;
        As[(k4 + 3) * 32 + si] = -2.f * v.w;
    }

    float bestv[4]; int bestj[4];
#pragma unroll
    for (int i = 0; i < 4; i++) { bestv[i] = -FLT_MAX; bestj[i] = 0; }

    for (int t = 0; t < 10; t++) {
        if (t < 9) asm volatile("cp.async.wait_group 1;");
        else       asm volatile("cp.async.wait_group 0;");
        __syncthreads();
        const float* bp = Bs + (t & 1) * RS_BW;
        const int j0 = j00 + t * 128;

        float acc[4][4];
#pragma unroll
        for (int g = 0; g < 4; g++) {
            float cn = __ldg(&g_cnorm[j0 + lane + 32 * g]);
#pragma unroll
            for (int si = 0; si < 4; si++) acc[si][g] = cn;
        }
#pragma unroll 4
        for (int k = 0; k < DIM; k++) {
            float4 a4 = *(const float4*)&As[k * 32 + 4 * w];
            float a[4] = {a4.x, a4.y, a4.z, a4.w};
#pragma unroll
            for (int g = 0; g < 4; g++) {
                float b = bp[k * 128 + lane + 32 * g];
#pragma unroll
                for (int si = 0; si < 4; si++) acc[si][g] = fmaf(a[si], b, acc[si][g]);
            }
        }
#pragma unroll
        for (int g = 0; g < 4; g++) {
            int j = j0 + lane + 32 * g;
#pragma unroll
            for (int si = 0; si < 4; si++) {
                if (acc[si][g] > bestv[si]) { bestv[si] = acc[si][g]; bestj[si] = j; }
            }
        }
        __syncthreads();
        if (t + 2 < 10) issueB(t + 2);
    }

#pragma unroll
    for (int si = 0; si < 4; si++) {
        float v = bestv[si]; int bj = bestj[si];
#pragma unroll
        for (int off = 16; off > 0; off >>= 1) {
            float ov = __shfl_xor_sync(0xFFFFFFFFu, v, off);
            int   oj = __shfl_xor_sync(0xFFFFFFFFu, bj, off);
            if (ov > v || (ov == v && oj < bj)) { v = ov; bj = oj; }
        }
        int gi = 4 * w + si;
        if (lane == 0 && gi < nval)
            atomicMax(&g_best[g_rescue_list[sb * 32 + gi]], enc_best(v, bj));
    }
}

// ---------------- gather: quantize/index/diff outputs ----------------
__global__ void gather_kernel(const float* __restrict__ A,
                              const float* __restrict__ Bm,
                              float* __restrict__ out) {
    const int w = threadIdx.x >> 5, lane = threadIdx.x & 31;
    const int s = blockIdx.x * 8 + w;
    const int j = (int)(unsigned)(~(unsigned)g_best[s]);
    float sum = 0.f;
#pragma unroll
    for (int r = 0; r < 4; r++) {
        const int d = lane + r * 32;
        float q = __ldg(&Bm[d * N_EMBED + j]);
        out[s * DIM + d] = q;
        float x = A[s * DIM + d];
        float t = x - q;
        sum += t * t;
    }
#pragma unroll
    for (int off = 16; off > 0; off >>= 1)
        sum += __shfl_xor_sync(0xFFFFFFFFu, sum, off);
    if (lane == 0) {
        out[N_SAMPLES * DIM + s] = (float)j;
        out[N_SAMPLES * (DIM + 1) + s] = sum * (1.0f / DIM);
    }
}

extern "C" void kernel_launch(void* const* d_in, const int* in_sizes, int n_in,
                              void* d_out, int out_size) {
    const float* A  = (const float*)d_in[0];
    const float* Bm = (const float*)d_in[1];
    if (n_in >= 2 && in_sizes[0] == DIM * N_EMBED) {
        const float* t = A; A = Bm; Bm = t;
    }
    float* out = (float*)d_out;

    static int attr_set = 0;
    if (!attr_set) {
        cudaFuncSetAttribute(phase1_kernel,
            cudaFuncAttributeMaxDynamicSharedMemorySize, SMEM_WORDS * 4);
        cudaFuncSetAttribute(rescue_kernel,
            cudaFuncAttributeMaxDynamicSharedMemorySize, (RS_AW + 2 * RS_BW) * 4);
        attr_set = 1;
    }

    cnorm_kernel<<<N_EMBED_PAD / 64, 256>>>(Bm);
    dim3 gB(N_EMBED_PAD / 32, DIM / 32), bB(32, 8);
    prep_b_kernel<<<gB, bB>>>(Bm);
    prep_aeps_kernel<<<N_SAMPLES / 8, 256>>>(A);
    phase1_kernel<<<128 * NSLICE, THREADS, SMEM_WORDS * 4>>>(A);
    combine_kernel<<<N_SAMPLES / 256, 256>>>();
    rescue_kernel<<<2048, 256, (RS_AW + 2 * RS_BW) * 4>>>(A, Bm);
    gather_kernel<<<N_SAMPLES / 8, 256>>>(A, Bm, out);
}

// round 14
// speedup vs baseline: 1.0218x; 1.0218x over previous
#include <cuda_runtime.h>
#include <float.h>
#include <stdint.h>

#define DIM 128
#define N_SAMPLES 8192
#define N_EMBED 10000
#define N_EMBED_PAD 10240
#define TM 64
#define TN 128
#define THREADS 256
#define NSLICE 16
#define SLICE_W 640
#define NCH 5

typedef unsigned long long u64;

__device__ float    g_cnorm[N_EMBED_PAD];
__device__ u64      g_best[N_SAMPLES];
__device__ __align__(256) uint32_t g_bT[N_EMBED_PAD * (DIM / 2)];  // fp16 [n][k] word-packed
__device__ u64      g_t1[NSLICE * N_SAMPLES];
__device__ float    g_t2[NSLICE * N_SAMPLES];
__device__ float    g_eps[N_SAMPLES];
__device__ unsigned g_maxbhi, g_maxblo;
__device__ int      g_rescue_count;
__device__ int      g_rescue_list[N_SAMPLES];

__device__ __forceinline__ unsigned smem_u32(const void* p) {
    return (unsigned)__cvta_generic_to_shared(p);
}
__device__ __forceinline__ void cp16(unsigned dst, const void* src) {
    asm volatile("cp.async.cg.shared.global [%0], [%1], 16;" :: "r"(dst), "l"(src));
}
__device__ __forceinline__ void cp16z(unsigned dst, const void* src, int sz) {
    asm volatile("cp.async.cg.shared.global [%0], [%1], 16, %2;"
                 :: "r"(dst), "l"(src), "r"(sz));
}
__device__ __forceinline__ u64 enc_best(float v, int j) {
    unsigned b = __float_as_uint(v);
    b = ((int)b < 0) ? ~b : (b | 0x80000000u);
    return ((u64)b << 32) | (unsigned)(~j);
}
__device__ __forceinline__ float dec_val(u64 p) {
    unsigned b = (unsigned)(p >> 32);
    unsigned f = (b & 0x80000000u) ? (b ^ 0x80000000u) : ~b;
    return __uint_as_float(f);
}
__device__ __forceinline__ float f16rt(float v, float* lo) {
    unsigned short hb; float hf;
    asm("cvt.rn.f16.f32 %0, %1;" : "=h"(hb) : "f"(v));
    asm("cvt.f32.f16 %0, %1;"    : "=f"(hf) : "h"(hb));
    *lo = v - hf;
    return hf;
}
__device__ __forceinline__ unsigned short f16of(float v) {
    unsigned short hb;
    asm("cvt.rn.f16.f32 %0, %1;" : "=h"(hb) : "f"(v));
    return hb;
}
__device__ __forceinline__ void hsplit2hi(float x, float y, uint32_t& hw) {
    hw = (uint32_t)f16of(x) | ((uint32_t)f16of(y) << 16);
}
__device__ __forceinline__ void mma_f16(float* d, uint4 a, uint32_t b0, uint32_t b1) {
    asm volatile(
        "mma.sync.aligned.m16n8k16.row.col.f32.f16.f16.f32 "
        "{%0,%1,%2,%3}, {%4,%5,%6,%7}, {%8,%9}, {%0,%1,%2,%3};"
        : "+f"(d[0]), "+f"(d[1]), "+f"(d[2]), "+f"(d[3])
        : "r"(a.x), "r"(a.y), "r"(a.z), "r"(a.w), "r"(b0), "r"(b1));
}
__device__ __forceinline__ void ldmx4(uint32_t& r0, uint32_t& r1, uint32_t& r2,
                                      uint32_t& r3, unsigned addr) {
    asm volatile("ldmatrix.sync.aligned.m8n8.x4.shared.b16 {%0,%1,%2,%3}, [%4];"
                 : "=r"(r0), "=r"(r1), "=r"(r2), "=r"(r3) : "r"(addr));
}

// ---------------- prep: cnorm + b-split norm maxes + counter reset ----------------
__global__ void cnorm_kernel(const float* __restrict__ cm) {
    __shared__ float red[3][4][64];
    __shared__ unsigned mhi, mlo;
    const int tid = threadIdx.x;
    const int jl  = tid & 63;
    const int dc  = tid >> 6;
    const int j   = blockIdx.x * 64 + jl;
    if (tid == 0) { mhi = 0; mlo = 0; }
    if (blockIdx.x == 0 && tid == 0) g_rescue_count = 0;
    __syncthreads();
    float s_cn = 0.f, s_hi = 0.f, s_lo = 0.f;
    if (j < N_EMBED) {
#pragma unroll 8
        for (int dd = 0; dd < 32; dd++) {
            float v = cm[(dc * 32 + dd) * N_EMBED + j];
            float lo, hf = f16rt(v, &lo);
            s_cn += v * v; s_hi += hf * hf; s_lo += lo * lo;
        }
    }
    red[0][dc][jl] = s_cn; red[1][dc][jl] = s_hi; red[2][dc][jl] = s_lo;
    __syncthreads();
    if (dc == 0) {
        float cn = red[0][0][jl] + red[0][1][jl] + red[0][2][jl] + red[0][3][jl];
        float hi = red[1][0][jl] + red[1][1][jl] + red[1][2][jl] + red[1][3][jl];
        float lo = red[2][0][jl] + red[2][1][jl] + red[2][2][jl] + red[2][3][jl];
        g_cnorm[j] = (j < N_EMBED) ? cn : -1e30f;
        if (j < N_EMBED) {
            atomicMax(&mhi, __float_as_uint(hi));
            atomicMax(&mlo, __float_as_uint(lo));
        }
    }
    __syncthreads();
    if (tid == 0) {
        atomicMax(&g_maxbhi, mhi);
        atomicMax(&g_maxblo, mlo);
    }
}

// Transpose cluster_mean [k][j] fp32 -> g_bT [j][k] fp16 word-packed (zero pad).
__global__ void prep_b_kernel(const float* __restrict__ cm) {
    __shared__ unsigned short t[32][34];
    const int jt = blockIdx.x, kt = blockIdx.y;
    const int tx = threadIdx.x, ty = threadIdx.y;   // (32, 8)
#pragma unroll
    for (int r = 0; r < 4; r++) {
        int k = kt * 32 + ty + r * 8;
        int j = jt * 32 + tx;
        float v = (j < N_EMBED) ? cm[k * N_EMBED + j] : 0.f;
        t[ty + r * 8][tx] = f16of(v);
    }
    __syncthreads();
    const int tid = ty * 32 + tx;
#pragma unroll
    for (int r = 0; r < 2; r++) {
        int i  = tid + r * 256;
        int jl = i >> 4;
        int w  = i & 15;
        uint32_t word = (uint32_t)t[2 * w][jl] | ((uint32_t)t[2 * w + 1][jl] << 16);
        g_bT[(size_t)(jt * 32 + jl) * (DIM / 2) + kt * 16 + w] = word;
    }
}

// Per-sample sound error bound.
__global__ void prep_aeps_kernel(const float* __restrict__ A) {
    const int w = threadIdx.x >> 5, lane = threadIdx.x & 31;
    const int s = blockIdx.x * 8 + w;
    float shi = 0.f, slo = 0.f;
#pragma unroll
    for (int r = 0; r < 4; r++) {
        float a = -2.f * A[s * DIM + lane + 32 * r];
        float lo, hf = f16rt(a, &lo);
        shi += hf * hf; slo += lo * lo;
    }
#pragma unroll
    for (int off = 16; off > 0; off >>= 1) {
        shi += __shfl_xor_sync(0xFFFFFFFFu, shi, off);
        slo += __shfl_xor_sync(0xFFFFFFFFu, slo, off);
    }
    if (lane == 0) {
        float MBHI = sqrtf(__uint_as_float(g_maxbhi));
        float MBLO = sqrtf(__uint_as_float(g_maxblo));
        float nlo = sqrtf(slo), nhi = sqrtf(shi);
        g_eps[s] = 2.0002f * (nlo * MBHI + nhi * MBLO + nlo * MBLO) + 0.02f;
    }
}

// ---------------- phase1: hi-only mma, warp tile 32m x 32n, TN=128 ------------
#define AW     4096
#define BROW   68                        // words/row (272B -> conflict-free ldmatrix)
#define BHALF  (TN * BROW)               // 8704 words per buffer
#define SMEM_WORDS (AW + 2 * BHALF + 768)   // 22272 words = 89KB

__global__ __launch_bounds__(THREADS, 2)
void phase1_kernel(const float* __restrict__ A) {
    extern __shared__ uint32_t smw[];
    uint32_t* Aw = smw;
    uint32_t* Bw = smw + AW;
    u64*   mt1 = (u64*)(smw + AW + 2 * BHALF);
    float* mt2 = (float*)(smw + AW + 2 * BHALF + 512);

    const int tid  = threadIdx.x;
    const int lane = tid & 31;
    const int sy   = tid >> 5;           // 8 warps: 2 m-groups x 4 n-groups
    const int wm   = sy >> 2;            // 0..1
    const int wn   = sy & 3;             // 0..3 -> 32-col group
    const int n0w  = wn * 32;
    const int mtg0 = wm * 2;
    const int tig  = lane & 3;

    const int mt  = blockIdx.x & 127;
    const int sl  = blockIdx.x >> 7;
    const int m0  = mt * TM;
    const int j00 = sl * SLICE_W;

    // ldmatrix row addresses (two x4 loads per ks: n0w..+15 and n0w+16..+31)
    const int lm  = lane >> 3, lr = lane & 7;
    const int lrow = n0w + ((lm >> 1) & 1) * 8 + lr;
    const int lkb  = (lm & 1) * 8;
    const unsigned bbase0 = smem_u32(Bw) + lrow * (BROW * 4) + lkb * 2;
    const unsigned bbase1 = bbase0 + 16 * (BROW * 4);

    auto issueB = [&](int t) {
        const int j0 = j00 + t * TN;
        uint32_t* dst = Bw + (t & 1) * BHALF;
        for (int i = tid; i < 2048; i += THREADS) {   // 8 iters
            int r = i >> 4, s = i & 15;
            cp16(smem_u32(dst + r * BROW + s * 4),
                 g_bT + (size_t)(j0 + r) * (DIM / 2) + s * 4);
        }
        asm volatile("cp.async.commit_group;");
    };

    issueB(0);
    issueB(1);

    // A hi split into smem, fragment-major (1 LDS.128 per fragment).
    for (int i = tid; i < 1024; i += THREADS) {
        int li = i & 31;
        int ks = (i >> 5) & 7;
        int mq = i >> 8;
        int r = li >> 2, tg = li & 3;
        int row0 = m0 + mq * 16 + r;
        int c0 = ks * 16 + 2 * tg;
        const float* A0 = A + (size_t)row0 * DIM;
        const float* A1 = A0 + 8 * DIM;
        uint32_t h0, h1, h2, h3;
        hsplit2hi(-2.f * A0[c0],     -2.f * A0[c0 + 1], h0);
        hsplit2hi(-2.f * A1[c0],     -2.f * A1[c0 + 1], h1);
        hsplit2hi(-2.f * A0[c0 + 8], -2.f * A0[c0 + 9], h2);
        hsplit2hi(-2.f * A1[c0 + 8], -2.f * A1[c0 + 9], h3);
        *(uint4*)&Aw[((mq * 8 + ks) * 32 + li) * 4] = make_uint4(h0, h1, h2, h3);
    }

    float b1[4], b2[4];
    int   j1[4];
#pragma unroll
    for (int i = 0; i < 4; i++) { b1[i] = -FLT_MAX; b2[i] = -FLT_MAX; j1[i] = 0; }

    for (int t = 0; t < NCH; t++) {
        if (t < NCH - 1) asm volatile("cp.async.wait_group 1;");
        else             asm volatile("cp.async.wait_group 0;");
        __syncthreads();                 // chunk t + A tile resident

        const unsigned ba0 = bbase0 + (t & 1) * (BHALF * 4);
        const unsigned ba1 = bbase1 + (t & 1) * (BHALF * 4);
        const int j0 = j00 + t * TN;

        // acc[mq][nt][4]; nt = 4 n8-tiles; init with cnorm.
        float acc[2][4][4];
#pragma unroll
        for (int nt = 0; nt < 4; nt++) {
            int c0 = j0 + n0w + nt * 8 + 2 * tig;
            float cn0 = __ldg(&g_cnorm[c0]);
            float cn1 = __ldg(&g_cnorm[c0 + 1]);
#pragma unroll
            for (int mq = 0; mq < 2; mq++) {
                acc[mq][nt][0] = cn0; acc[mq][nt][1] = cn1;
                acc[mq][nt][2] = cn0; acc[mq][nt][3] = cn1;
            }
        }

#pragma unroll
        for (int ks = 0; ks < 8; ks++) {
            uint4 ah0 = *(const uint4*)&Aw[(((mtg0 + 0) * 8 + ks) * 32 + lane) * 4];
            uint4 ah1 = *(const uint4*)&Aw[(((mtg0 + 1) * 8 + ks) * 32 + lane) * 4];
            uint32_t b00, b01, b02, b03, b10, b11, b12, b13;
            ldmx4(b00, b01, b02, b03, ba0 + ks * 32);
            ldmx4(b10, b11, b12, b13, ba1 + ks * 32);
            mma_f16(acc[0][0], ah0, b00, b01);
            mma_f16(acc[1][0], ah1, b00, b01);
            mma_f16(acc[0][1], ah0, b02, b03);
            mma_f16(acc[1][1], ah1, b02, b03);
            mma_f16(acc[0][2], ah0, b10, b11);
            mma_f16(acc[1][2], ah1, b10, b11);
            mma_f16(acc[0][3], ah0, b12, b13);
            mma_f16(acc[1][3], ah1, b12, b13);
        }

        // top-2 update (ascending j preserves first-occurrence for top1).
#pragma unroll
        for (int nt = 0; nt < 4; nt++) {
            int c0 = j0 + n0w + nt * 8 + 2 * tig;
#pragma unroll
            for (int mq = 0; mq < 2; mq++) {
#pragma unroll
                for (int rb = 0; rb < 2; rb++) {
                    int st = mq * 2 + rb;
                    float v0 = acc[mq][nt][rb * 2 + 0];
                    float v1 = acc[mq][nt][rb * 2 + 1];
                    if (v0 > b1[st]) { b2[st] = b1[st]; b1[st] = v0; j1[st] = c0; }
                    else if (v0 > b2[st]) b2[st] = v0;
                    if (v1 > b1[st]) { b2[st] = b1[st]; b1[st] = v1; j1[st] = c0 + 1; }
                    else if (v1 > b2[st]) b2[st] = v1;
                }
            }
        }

        __syncthreads();
        if (t + 2 < NCH) issueB(t + 2);
    }

    // quad merge, stash per-wn, cross-warp merge.
#pragma unroll
    for (int s = 0; s < 4; s++) {
        float v = b1[s], v2 = b2[s];
        int   bj = j1[s];
#pragma unroll
        for (int off = 1; off < 4; off <<= 1) {
            float ov  = __shfl_xor_sync(0xFFFFFFFFu, v, off);
            int   oj  = __shfl_xor_sync(0xFFFFFFFFu, bj, off);
            float ov2 = __shfl_xor_sync(0xFFFFFFFFu, v2, off);
            float nv2 = fmaxf(fmaxf(v2, ov2), fminf(v, ov));
            if (ov > v || (ov == v && oj < bj)) { v = ov; bj = oj; }
            v2 = nv2;
        }
        if ((lane & 3) == 0) {
            int mq = s >> 1, rb = s & 1;
            int rl = (mtg0 + mq) * 16 + (lane >> 2) + rb * 8;
            mt1[wn * 64 + rl] = enc_best(v, bj);
            mt2[wn * 64 + rl] = v2;
        }
    }
    __syncthreads();
    if (tid < 64) {
        int r = tid;
        u64 m = mt1[r]; int wi = 0;
        for (int w = 1; w < 4; w++) {
            u64 t = mt1[w * 64 + r];
            if (t > m) { m = t; wi = w; }
        }
        float v2 = -FLT_MAX;
        for (int w = 0; w < 4; w++) {
            float c = (w == wi) ? mt2[w * 64 + r]
                                : fmaxf(dec_val(mt1[w * 64 + r]), mt2[w * 64 + r]);
            v2 = fmaxf(v2, c);
        }
        g_t1[sl * N_SAMPLES + m0 + r] = m;
        g_t2[sl * N_SAMPLES + m0 + r] = v2;
    }
}

// ---------------- combine: global top-2, gap test, rescue list ----------------
__global__ void combine_kernel() {
    const int s = blockIdx.x * 256 + threadIdx.x;
    u64 m1 = 0; int i1 = 0;
#pragma unroll
    for (int i = 0; i < NSLICE; i++) {
        u64 t = g_t1[i * N_SAMPLES + s];
        if (t > m1) { m1 = t; i1 = i; }
    }
    float v1 = dec_val(m1);
    float v2 = -FLT_MAX;
#pragma unroll
    for (int i = 0; i < NSLICE; i++) {
        float c = (i == i1) ? g_t2[i * N_SAMPLES + s]
                            : fmaxf(dec_val(g_t1[i * N_SAMPLES + s]),
                                    g_t2[i * N_SAMPLES + s]);
        v2 = fmaxf(v2, c);
    }
    if (v1 - v2 > g_eps[s]) {
        g_best[s] = m1;
    } else {
        g_best[s] = 0;
        int p = atomicAdd(&g_rescue_count, 1);
        g_rescue_list[p] = s;
    }
}

// ---------------- rescue: exact fp32 re-scan for contested samples ----------------
#define RS_AW 4096
#define RS_BW 16384
__global__ __launch_bounds__(256)
void rescue_kernel(const float* __restrict__ A, const float* __restrict__ Bm) {
    const int cnt = *(volatile int*)&g_rescue_count;
    const int sb = blockIdx.x >> 3, sl = blockIdx.x & 7;
    if (sb * 32 >= cnt) return;
    const int nval = min(32, cnt - sb * 32);

    extern __shared__ float smf[];
    float* As = smf;
    float* Bs = smf + RS_AW;

    const int tid = threadIdx.x, lane = tid & 31, w = tid >> 5;
    const int j00 = sl * 1280;

    auto issueB = [&](int t) {
        const int j0 = j00 + t * 128;
        float* dst = Bs + (t & 1) * RS_BW;
        for (int i = tid; i < 4096; i += 256) {
            int k = i >> 5, j4 = (i & 31) * 4;
            int j = j0 + j4;
            cp16z(smem_u32(dst + k * 128 + j4),
                  Bm + (size_t)k * N_EMBED + min(j, N_EMBED - 4),
                  (j < N_EMBED) ? 16 : 0);
        }
        asm volatile("cp.async.commit_group;");
    };

    issueB(0);
    issueB(1);

    for (int i = tid; i < 1024; i += 256) {
        int si = i >> 5, k4 = (i & 31) * 4;
        float4 v = make_float4(0.f, 0.f, 0.f, 0.f);
        if (si < nval) {
            int s = g_rescue_list[sb * 32 + si];
            v = *(const float4*)&A[(size_t)s * DIM + k4];
        }
        As[(k4 + 0) * 32 + si] = -2.f * v.x;
        As[(k4 + 1) * 32 + si] = -2.f * v.y;
        As[(k4 + 2) * 32 + si] = -2.f * v.z;
        As[(k4 + 3) * 32 + si] = -2.f * v.w;
    }

    float bestv[4]; int bestj[4];
#pragma unroll
    for (int i = 0; i < 4; i++) { bestv[i] = -FLT_MAX; bestj[i] = 0; }

    for (int t = 0; t < 10; t++) {
        if (t < 9) asm volatile("cp.async.wait_group 1;");
        else       asm volatile("cp.async.wait_group 0;");
        __syncthreads();
        const float* bp = Bs + (t & 1) * RS_BW;
        const int j0 = j00 + t * 128;

        float acc[4][4];
#pragma unroll
        for (int g = 0; g < 4; g++) {
            float cn = __ldg(&g_cnorm[j0 + lane + 32 * g]);
#pragma unroll
            for (int si = 0; si < 4; si++) acc[si][g] = cn;
        }
#pragma unroll 4
        for (int k = 0; k < DIM; k++) {
            float4 a4 = *(const float4*)&As[k * 32 + 4 * w];
            float a[4] = {a4.x, a4.y, a4.z, a4.w};
#pragma unroll
            for (int g = 0; g < 4; g++) {
                float b = bp[k * 128 + lane + 32 * g];
#pragma unroll
                for (int si = 0; si < 4; si++) acc[si][g] = fmaf(a[si], b, acc[si][g]);
            }
        }
#pragma unroll
        for (int g = 0; g < 4; g++) {
            int j = j0 + lane + 32 * g;
#pragma unroll
            for (int si = 0; si < 4; si++) {
                if (acc[si][g] > bestv[si]) { bestv[si] = acc[si][g]; bestj[si] = j; }
            }
        }
        __syncthreads();
        if (t + 2 < 10) issueB(t + 2);
    }

#pragma unroll
    for (int si = 0; si < 4; si++) {
        float v = bestv[si]; int bj = bestj[si];
#pragma unroll
        for (int off = 16; off > 0; off >>= 1) {
            float ov = __shfl_xor_sync(0xFFFFFFFFu, v, off);
            int   oj = __shfl_xor_sync(0xFFFFFFFFu, bj, off);
            if (ov > v || (ov == v && oj < bj)) { v = ov; bj = oj; }
        }
        int gi = 4 * w + si;
        if (lane == 0 && gi < nval)
            atomicMax(&g_best[g_rescue_list[sb * 32 + gi]], enc_best(v, bj));
    }
}

// ---------------- gather: quantize/index/diff outputs ----------------
__global__ void gather_kernel(const float* __restrict__ A,
                              const float* __restrict__ Bm,
                              float* __restrict__ out) {
    const int w = threadIdx.x >> 5, lane = threadIdx.x & 31;
    const int s = blockIdx.x * 8 + w;
    const int j = (int)(unsigned)(~(unsigned)g_best[s]);
    float sum = 0.f;
#pragma unroll
    for (int r = 0; r < 4; r++) {
        const int d = lane + r * 32;
        float q = __ldg(&Bm[d * N_EMBED + j]);
        out[s * DIM + d] = q;
        float x = A[s * DIM + d];
        float t = x - q;
        sum += t * t;
    }
#pragma unroll
    for (int off = 16; off > 0; off >>= 1)
        sum += __shfl_xor_sync(0xFFFFFFFFu, sum, off);
    if (lane == 0) {
        out[N_SAMPLES * DIM + s] = (float)j;
        out[N_SAMPLES * (DIM + 1) + s] = sum * (1.0f / DIM);
    }
}

extern "C" void kernel_launch(void* const* d_in, const int* in_sizes, int n_in,
                              void* d_out, int out_size) {
    const float* A  = (const float*)d_in[0];
    const float* Bm = (const float*)d_in[1];
    if (n_in >= 2 && in_sizes[0] == DIM * N_EMBED) {
        const float* t = A; A = Bm; Bm = t;
    }
    float* out = (float*)d_out;

    static int attr_set = 0;
    if (!attr_set) {
        cudaFuncSetAttribute(phase1_kernel,
            cudaFuncAttributeMaxDynamicSharedMemorySize, SMEM_WORDS * 4);
        cudaFuncSetAttribute(rescue_kernel,
            cudaFuncAttributeMaxDynamicSharedMemorySize, (RS_AW + 2 * RS_BW) * 4);
        attr_set = 1;
    }

    cnorm_kernel<<<N_EMBED_PAD / 64, 256>>>(Bm);
    dim3 gB(N_EMBED_PAD / 32, DIM / 32), bB(32, 8);
    prep_b_kernel<<<gB, bB>>>(Bm);
    prep_aeps_kernel<<<N_SAMPLES / 8, 256>>>(A);
    phase1_kernel<<<128 * NSLICE, THREADS, SMEM_WORDS * 4>>>(A);
    combine_kernel<<<N_SAMPLES / 256, 256>>>();
    rescue_kernel<<<2048, 256, (RS_AW + 2 * RS_BW) * 4>>>(A, Bm);
    gather_kernel<<<N_SAMPLES / 8, 256>>>(A, Bm, out);
}

// round 15
// speedup vs baseline: 1.1202x; 1.0963x over previous
#include <cuda_runtime.h>
#include <float.h>
#include <stdint.h>

#define DIM 128
#define N_SAMPLES 8192
#define N_EMBED 10000
#define N_EMBED_PAD 10240
#define TM 128
#define TN 64
#define THREADS 256
#define NSLICE 16
#define SLICE_W 640
#define NCH 10

typedef unsigned long long u64;

__device__ float    g_cnorm[N_EMBED_PAD];
__device__ u64      g_best[N_SAMPLES];
__device__ __align__(256) uint32_t g_bT[N_EMBED_PAD * (DIM / 2)];  // fp16 [n][k] word-packed
__device__ u64      g_t1[NSLICE * N_SAMPLES];
__device__ float    g_t2[NSLICE * N_SAMPLES];
__device__ float    g_eps[N_SAMPLES];
__device__ unsigned g_maxbhi, g_maxblo;
__device__ int      g_rescue_count;
__device__ int      g_rescue_list[N_SAMPLES];

__device__ __forceinline__ unsigned smem_u32(const void* p) {
    return (unsigned)__cvta_generic_to_shared(p);
}
__device__ __forceinline__ void cp16(unsigned dst, const void* src) {
    asm volatile("cp.async.cg.shared.global [%0], [%1], 16;" :: "r"(dst), "l"(src));
}
__device__ __forceinline__ void cp16z(unsigned dst, const void* src, int sz) {
    asm volatile("cp.async.cg.shared.global [%0], [%1], 16, %2;"
                 :: "r"(dst), "l"(src), "r"(sz));
}
__device__ __forceinline__ u64 enc_best(float v, int j) {
    unsigned b = __float_as_uint(v);
    b = ((int)b < 0) ? ~b : (b | 0x80000000u);
    return ((u64)b << 32) | (unsigned)(~j);
}
__device__ __forceinline__ float dec_val(u64 p) {
    unsigned b = (unsigned)(p >> 32);
    unsigned f = (b & 0x80000000u) ? (b ^ 0x80000000u) : ~b;
    return __uint_as_float(f);
}
__device__ __forceinline__ float f16rt(float v, float* lo) {
    unsigned short hb; float hf;
    asm("cvt.rn.f16.f32 %0, %1;" : "=h"(hb) : "f"(v));
    asm("cvt.f32.f16 %0, %1;"    : "=f"(hf) : "h"(hb));
    *lo = v - hf;
    return hf;
}
__device__ __forceinline__ unsigned short f16of(float v) {
    unsigned short hb;
    asm("cvt.rn.f16.f32 %0, %1;" : "=h"(hb) : "f"(v));
    return hb;
}
__device__ __forceinline__ void hsplit2hi(float x, float y, uint32_t& hw) {
    hw = (uint32_t)f16of(x) | ((uint32_t)f16of(y) << 16);
}
__device__ __forceinline__ void mma_f16(float* d, uint4 a, uint32_t b0, uint32_t b1) {
    asm volatile(
        "mma.sync.aligned.m16n8k16.row.col.f32.f16.f16.f32 "
        "{%0,%1,%2,%3}, {%4,%5,%6,%7}, {%8,%9}, {%0,%1,%2,%3};"
        : "+f"(d[0]), "+f"(d[1]), "+f"(d[2]), "+f"(d[3])
        : "r"(a.x), "r"(a.y), "r"(a.z), "r"(a.w), "r"(b0), "r"(b1));
}
__device__ __forceinline__ void ldmx4(uint32_t& r0, uint32_t& r1, uint32_t& r2,
                                      uint32_t& r3, unsigned addr) {
    asm volatile("ldmatrix.sync.aligned.m8n8.x4.shared.b16 {%0,%1,%2,%3}, [%4];"
                 : "=r"(r0), "=r"(r1), "=r"(r2), "=r"(r3) : "r"(addr));
}

// ---------------- prep: cnorm + b-split norm maxes + counter reset ----------------
__global__ void cnorm_kernel(const float* __restrict__ cm) {
    __shared__ float red[3][4][64];
    __shared__ unsigned mhi, mlo;
    const int tid = threadIdx.x;
    const int jl  = tid & 63;
    const int dc  = tid >> 6;
    const int j   = blockIdx.x * 64 + jl;
    if (tid == 0) { mhi = 0; mlo = 0; }
    if (blockIdx.x == 0 && tid == 0) g_rescue_count = 0;
    __syncthreads();
    float s_cn = 0.f, s_hi = 0.f, s_lo = 0.f;
    if (j < N_EMBED) {
#pragma unroll 8
        for (int dd = 0; dd < 32; dd++) {
            float v = cm[(dc * 32 + dd) * N_EMBED + j];
            float lo, hf = f16rt(v, &lo);
            s_cn += v * v; s_hi += hf * hf; s_lo += lo * lo;
        }
    }
    red[0][dc][jl] = s_cn; red[1][dc][jl] = s_hi; red[2][dc][jl] = s_lo;
    __syncthreads();
    if (dc == 0) {
        float cn = red[0][0][jl] + red[0][1][jl] + red[0][2][jl] + red[0][3][jl];
        float hi = red[1][0][jl] + red[1][1][jl] + red[1][2][jl] + red[1][3][jl];
        float lo = red[2][0][jl] + red[2][1][jl] + red[2][2][jl] + red[2][3][jl];
        g_cnorm[j] = (j < N_EMBED) ? cn : -1e30f;
        if (j < N_EMBED) {
            atomicMax(&mhi, __float_as_uint(hi));
            atomicMax(&mlo, __float_as_uint(lo));
        }
    }
    __syncthreads();
    if (tid == 0) {
        atomicMax(&g_maxbhi, mhi);
        atomicMax(&g_maxblo, mlo);
    }
}

// Transpose cluster_mean [k][j] fp32 -> g_bT [j][k] fp16 word-packed (zero pad).
__global__ void prep_b_kernel(const float* __restrict__ cm) {
    __shared__ unsigned short t[32][34];
    const int jt = blockIdx.x, kt = blockIdx.y;
    const int tx = threadIdx.x, ty = threadIdx.y;   // (32, 8)
#pragma unroll
    for (int r = 0; r < 4; r++) {
        int k = kt * 32 + ty + r * 8;
        int j = jt * 32 + tx;
        float v = (j < N_EMBED) ? cm[k * N_EMBED + j] : 0.f;
        t[ty + r * 8][tx] = f16of(v);
    }
    __syncthreads();
    const int tid = ty * 32 + tx;
#pragma unroll
    for (int r = 0; r < 2; r++) {
        int i  = tid + r * 256;
        int jl = i >> 4;
        int w  = i & 15;
        uint32_t word = (uint32_t)t[2 * w][jl] | ((uint32_t)t[2 * w + 1][jl] << 16);
        g_bT[(size_t)(jt * 32 + jl) * (DIM / 2) + kt * 16 + w] = word;
    }
}

// Per-sample sound error bound.
__global__ void prep_aeps_kernel(const float* __restrict__ A) {
    const int w = threadIdx.x >> 5, lane = threadIdx.x & 31;
    const int s = blockIdx.x * 8 + w;
    float shi = 0.f, slo = 0.f;
#pragma unroll
    for (int r = 0; r < 4; r++) {
        float a = -2.f * A[s * DIM + lane + 32 * r];
        float lo, hf = f16rt(a, &lo);
        shi += hf * hf; slo += lo * lo;
    }
#pragma unroll
    for (int off = 16; off > 0; off >>= 1) {
        shi += __shfl_xor_sync(0xFFFFFFFFu, shi, off);
        slo += __shfl_xor_sync(0xFFFFFFFFu, slo, off);
    }
    if (lane == 0) {
        float MBHI = sqrtf(__uint_as_float(g_maxbhi));
        float MBLO = sqrtf(__uint_as_float(g_maxblo));
        float nlo = sqrtf(slo), nhi = sqrtf(shi);
        g_eps[s] = 2.0002f * (nlo * MBHI + nhi * MBLO + nlo * MBLO) + 0.02f;
    }
}

// ------- phase1: hi-only mma, TM=128 x TN=64, warp tile 32m x 32n, 3 CTAs/SM -------
#define AW     8192                      // A tile: 128 rows x 128 k fp16 = 32KB
#define BROW   68                        // words/row (272B -> conflict-free ldmatrix)
#define BHALF  (TN * BROW)               // 4352 words per buffer
#define SMEM_WORDS (AW + 2 * BHALF + 768)   // 17664 words = 70.7KB -> 3 CTAs/SM

__global__ __launch_bounds__(THREADS, 3)
void phase1_kernel(const float* __restrict__ A) {
    extern __shared__ uint32_t smw[];
    uint32_t* Aw = smw;
    uint32_t* Bw = smw + AW;
    u64*   mt1 = (u64*)(smw + AW + 2 * BHALF);   // [2 wn][128 rows]
    float* mt2 = (float*)(smw + AW + 2 * BHALF + 512);

    const int tid  = threadIdx.x;
    const int lane = tid & 31;
    const int sy   = tid >> 5;           // 8 warps: 4 m-groups x 2 n-groups
    const int wm   = sy & 3;             // 0..3
    const int wn   = sy >> 2;            // 0..1
    const int n0w  = wn * 32;
    const int mtg0 = wm * 2;             // warp's first m16-tile (of 8 in CTA)
    const int tig  = lane & 3;

    const int mt  = blockIdx.x & 63;
    const int sl  = blockIdx.x >> 6;
    const int m0  = mt * TM;
    const int j00 = sl * SLICE_W;

    // ldmatrix row addresses (two x4 loads per ks: n0w..+15, n0w+16..+31)
    const int lm  = lane >> 3, lr = lane & 7;
    const int lrow = n0w + ((lm >> 1) & 1) * 8 + lr;
    const int lkb  = (lm & 1) * 8;
    const unsigned bbase0 = smem_u32(Bw) + lrow * (BROW * 4) + lkb * 2;
    const unsigned bbase1 = bbase0 + 16 * (BROW * 4);

    auto issueB = [&](int t) {
        const int j0 = j00 + t * TN;
        uint32_t* dst = Bw + (t & 1) * BHALF;
        for (int i = tid; i < 1024; i += THREADS) {   // 4 iters
            int r = i >> 4, s = i & 15;
            cp16(smem_u32(dst + r * BROW + s * 4),
                 g_bT + (size_t)(j0 + r) * (DIM / 2) + s * 4);
        }
        asm volatile("cp.async.commit_group;");
    };

    issueB(0);
    issueB(1);

    // A hi split into smem, fragment-major (1 LDS.128 per fragment). 8 m16-tiles.
    for (int i = tid; i < 2048; i += THREADS) {      // 8 iters
        int li = i & 31;
        int ks = (i >> 5) & 7;
        int mq = i >> 8;                  // 0..7
        int r = li >> 2, tg = li & 3;
        int row0 = m0 + mq * 16 + r;
        int c0 = ks * 16 + 2 * tg;
        const float* A0 = A + (size_t)row0 * DIM;
        const float* A1 = A0 + 8 * DIM;
        uint32_t h0, h1, h2, h3;
        hsplit2hi(-2.f * A0[c0],     -2.f * A0[c0 + 1], h0);
        hsplit2hi(-2.f * A1[c0],     -2.f * A1[c0 + 1], h1);
        hsplit2hi(-2.f * A0[c0 + 8], -2.f * A0[c0 + 9], h2);
        hsplit2hi(-2.f * A1[c0 + 8], -2.f * A1[c0 + 9], h3);
        *(uint4*)&Aw[((mq * 8 + ks) * 32 + li) * 4] = make_uint4(h0, h1, h2, h3);
    }

    float b1[4], b2[4];
    int   j1[4];
#pragma unroll
    for (int i = 0; i < 4; i++) { b1[i] = -FLT_MAX; b2[i] = -FLT_MAX; j1[i] = 0; }

    for (int t = 0; t < NCH; t++) {
        if (t < NCH - 1) asm volatile("cp.async.wait_group 1;");
        else             asm volatile("cp.async.wait_group 0;");
        __syncthreads();                 // chunk t + A tile resident

        const unsigned ba0 = bbase0 + (t & 1) * (BHALF * 4);
        const unsigned ba1 = bbase1 + (t & 1) * (BHALF * 4);
        const int j0 = j00 + t * TN;

        // acc[mq][nt][4], zero-init; cnorm added in the top-2 epilogue
        // (covered by the +0.02 slack in eps -- certificate stays sound).
        float acc[2][4][4];
#pragma unroll
        for (int mq = 0; mq < 2; mq++)
#pragma unroll
            for (int nt = 0; nt < 4; nt++)
#pragma unroll
                for (int e = 0; e < 4; e++) acc[mq][nt][e] = 0.f;

        const uint32_t* ApW = Aw + (mtg0 * 8) * 128 + lane * 4;
#pragma unroll
        for (int ks = 0; ks < 8; ks++) {
            uint4 ah0 = *(const uint4*)(ApW + ks * 128);
            uint4 ah1 = *(const uint4*)(ApW + (8 + ks) * 128);
            uint32_t b00, b01, b02, b03, b10, b11, b12, b13;
            ldmx4(b00, b01, b02, b03, ba0 + ks * 32);
            ldmx4(b10, b11, b12, b13, ba1 + ks * 32);
            mma_f16(acc[0][0], ah0, b00, b01);
            mma_f16(acc[1][0], ah1, b00, b01);
            mma_f16(acc[0][1], ah0, b02, b03);
            mma_f16(acc[1][1], ah1, b02, b03);
            mma_f16(acc[0][2], ah0, b10, b11);
            mma_f16(acc[1][2], ah1, b10, b11);
            mma_f16(acc[0][3], ah0, b12, b13);
            mma_f16(acc[1][3], ah1, b12, b13);
        }

        // top-2 update with cnorm folded here (ascending j preserved).
#pragma unroll
        for (int nt = 0; nt < 4; nt++) {
            int c0 = j0 + n0w + nt * 8 + 2 * tig;
            float cn0 = __ldg(&g_cnorm[c0]);
            float cn1 = __ldg(&g_cnorm[c0 + 1]);
#pragma unroll
            for (int mq = 0; mq < 2; mq++) {
#pragma unroll
                for (int rb = 0; rb < 2; rb++) {
                    int st = mq * 2 + rb;
                    float v0 = acc[mq][nt][rb * 2 + 0] + cn0;
                    float v1 = acc[mq][nt][rb * 2 + 1] + cn1;
                    if (v0 > b1[st]) { b2[st] = b1[st]; b1[st] = v0; j1[st] = c0; }
                    else if (v0 > b2[st]) b2[st] = v0;
                    if (v1 > b1[st]) { b2[st] = b1[st]; b1[st] = v1; j1[st] = c0 + 1; }
                    else if (v1 > b2[st]) b2[st] = v1;
                }
            }
        }

        __syncthreads();
        if (t + 2 < NCH) issueB(t + 2);
    }

    // quad merge, stash per-wn, cross-warp merge over 2 n-groups.
#pragma unroll
    for (int s = 0; s < 4; s++) {
        float v = b1[s], v2 = b2[s];
        int   bj = j1[s];
#pragma unroll
        for (int off = 1; off < 4; off <<= 1) {
            float ov  = __shfl_xor_sync(0xFFFFFFFFu, v, off);
            int   oj  = __shfl_xor_sync(0xFFFFFFFFu, bj, off);
            float ov2 = __shfl_xor_sync(0xFFFFFFFFu, v2, off);
            float nv2 = fmaxf(fmaxf(v2, ov2), fminf(v, ov));
            if (ov > v || (ov == v && oj < bj)) { v = ov; bj = oj; }
            v2 = nv2;
        }
        if ((lane & 3) == 0) {
            int mq = s >> 1, rb = s & 1;
            int rl = (mtg0 + mq) * 16 + (lane >> 2) + rb * 8;   // 0..127
            mt1[wn * 128 + rl] = enc_best(v, bj);
            mt2[wn * 128 + rl] = v2;
        }
    }
    __syncthreads();
    if (tid < 128) {
        int r = tid;
        u64 m0v = mt1[r], m1v = mt1[128 + r];
        float s0 = mt2[r], s1 = mt2[128 + r];
        u64 m; float v2;
        if (m0v >= m1v) { m = m0v; v2 = fmaxf(s0, fmaxf(dec_val(m1v), s1)); }
        else            { m = m1v; v2 = fmaxf(s1, fmaxf(dec_val(m0v), s0)); }
        g_t1[sl * N_SAMPLES + m0 + r] = m;
        g_t2[sl * N_SAMPLES + m0 + r] = v2;
    }
}

// ---------------- combine: global top-2, gap test, rescue list ----------------
__global__ void combine_kernel() {
    const int s = blockIdx.x * 256 + threadIdx.x;
    u64 m1 = 0; int i1 = 0;
#pragma unroll
    for (int i = 0; i < NSLICE; i++) {
        u64 t = g_t1[i * N_SAMPLES + s];
        if (t > m1) { m1 = t; i1 = i; }
    }
    float v1 = dec_val(m1);
    float v2 = -FLT_MAX;
#pragma unroll
    for (int i = 0; i < NSLICE; i++) {
        float c = (i == i1) ? g_t2[i * N_SAMPLES + s]
                            : fmaxf(dec_val(g_t1[i * N_SAMPLES + s]),
                                    g_t2[i * N_SAMPLES + s]);
        v2 = fmaxf(v2, c);
    }
    if (v1 - v2 > g_eps[s]) {
        g_best[s] = m1;
    } else {
        g_best[s] = 0;
        int p = atomicAdd(&g_rescue_count, 1);
        g_rescue_list[p] = s;
    }
}

// ---------------- rescue: exact fp32 re-scan for contested samples ----------------
#define RS_AW 4096
#define RS_BW 16384
__global__ __launch_bounds__(256)
void rescue_kernel(const float* __restrict__ A, const float* __restrict__ Bm) {
    const int cnt = *(volatile int*)&g_rescue_count;
    const int sb = blockIdx.x >> 3, sl = blockIdx.x & 7;
    if (sb * 32 >= cnt) return;
    const int nval = min(32, cnt - sb * 32);

    extern __shared__ float smf[];
    float* As = smf;
    float* Bs = smf + RS_AW;

    const int tid = threadIdx.x, lane = tid & 31, w = tid >> 5;
    const int j00 = sl * 1280;

    auto issueB = [&](int t) {
        const int j0 = j00 + t * 128;
        float* dst = Bs + (t & 1) * RS_BW;
        for (int i = tid; i < 4096; i += 256) {
            int k = i >> 5, j4 = (i & 31) * 4;
            int j = j0 + j4;
            cp16z(smem_u32(dst + k * 128 + j4),
                  Bm + (size_t)k * N_EMBED + min(j, N_EMBED - 4),
                  (j < N_EMBED) ? 16 : 0);
        }
        asm volatile("cp.async.commit_group;");
    };

    issueB(0);
    issueB(1);

    for (int i = tid; i < 1024; i += 256) {
        int si = i >> 5, k4 = (i & 31) * 4;
        float4 v = make_float4(0.f, 0.f, 0.f, 0.f);
        if (si < nval) {
            int s = g_rescue_list[sb * 32 + si];
            v = *(const float4*)&A[(size_t)s * DIM + k4];
        }
        As[(k4 + 0) * 32 + si] = -2.f * v.x;
        As[(k4 + 1) * 32 + si] = -2.f * v.y;
        As[(k4 + 2) * 32 + si] = -2.f * v.z;
        As[(k4 + 3) * 32 + si] = -2.f * v.w;
    }

    float bestv[4]; int bestj[4];
#pragma unroll
    for (int i = 0; i < 4; i++) { bestv[i] = -FLT_MAX; bestj[i] = 0; }

    for (int t = 0; t < 10; t++) {
        if (t < 9) asm volatile("cp.async.wait_group 1;");
        else       asm volatile("cp.async.wait_group 0;");
        __syncthreads();
        const float* bp = Bs + (t & 1) * RS_BW;
        const int j0 = j00 + t * 128;

        float acc[4][4];
#pragma unroll
        for (int g = 0; g < 4; g++) {
            float cn = __ldg(&g_cnorm[j0 + lane + 32 * g]);
#pragma unroll
            for (int si = 0; si < 4; si++) acc[si][g] = cn;
        }
#pragma unroll 4
        for (int k = 0; k < DIM; k++) {
            float4 a4 = *(const float4*)&As[k * 32 + 4 * w];
            float a[4] = {a4.x, a4.y, a4.z, a4.w};
#pragma unroll
            for (int g = 0; g < 4; g++) {
                float b = bp[k * 128 + lane + 32 * g];
#pragma unroll
                for (int si = 0; si < 4; si++) acc[si][g] = fmaf(a[si], b, acc[si][g]);
            }
        }
#pragma unroll
        for (int g = 0; g < 4; g++) {
            int j = j0 + lane + 32 * g;
#pragma unroll
            for (int si = 0; si < 4; si++) {
                if (acc[si][g] > bestv[si]) { bestv[si] = acc[si][g]; bestj[si] = j; }
            }
        }
        __syncthreads();
        if (t + 2 < 10) issueB(t + 2);
    }

#pragma unroll
    for (int si = 0; si < 4; si++) {
        float v = bestv[si]; int bj = bestj[si];
#pragma unroll
        for (int off = 16; off > 0; off >>= 1) {
            float ov = __shfl_xor_sync(0xFFFFFFFFu, v, off);
            int   oj = __shfl_xor_sync(0xFFFFFFFFu, bj, off);
            if (ov > v || (ov == v && oj < bj)) { v = ov; bj = oj; }
        }
        int gi = 4 * w + si;
        if (lane == 0 && gi < nval)
            atomicMax(&g_best[g_rescue_list[sb * 32 + gi]], enc_best(v, bj));
    }
}

// ---------------- gather: quantize/index/diff outputs ----------------
__global__ void gather_kernel(const float* __restrict__ A,
                              const float* __restrict__ Bm,
                              float* __restrict__ out) {
    const int w = threadIdx.x >> 5, lane = threadIdx.x & 31;
    const int s = blockIdx.x * 8 + w;
    const int j = (int)(unsigned)(~(unsigned)g_best[s]);
    float sum = 0.f;
#pragma unroll
    for (int r = 0; r < 4; r++) {
        const int d = lane + r * 32;
        float q = __ldg(&Bm[d * N_EMBED + j]);
        out[s * DIM + d] = q;
        float x = A[s * DIM + d];
        float t = x - q;
        sum += t * t;
    }
#pragma unroll
    for (int off = 16; off > 0; off >>= 1)
        sum += __shfl_xor_sync(0xFFFFFFFFu, sum, off);
    if (lane == 0) {
        out[N_SAMPLES * DIM + s] = (float)j;
        out[N_SAMPLES * (DIM + 1) + s] = sum * (1.0f / DIM);
    }
}

extern "C" void kernel_launch(void* const* d_in, const int* in_sizes, int n_in,
                              void* d_out, int out_size) {
    const float* A  = (const float*)d_in[0];
    const float* Bm = (const float*)d_in[1];
    if (n_in >= 2 && in_sizes[0] == DIM * N_EMBED) {
        const float* t = A; A = Bm; Bm = t;
    }
    float* out = (float*)d_out;

    static int attr_set = 0;
    if (!attr_set) {
        cudaFuncSetAttribute(phase1_kernel,
            cudaFuncAttributeMaxDynamicSharedMemorySize, SMEM_WORDS * 4);
        cudaFuncSetAttribute(rescue_kernel,
            cudaFuncAttributeMaxDynamicSharedMemorySize, (RS_AW + 2 * RS_BW) * 4);
        attr_set = 1;
    }

    cnorm_kernel<<<N_EMBED_PAD / 64, 256>>>(Bm);
    dim3 gB(N_EMBED_PAD / 32, DIM / 32), bB(32, 8);
    prep_b_kernel<<<gB, bB>>>(Bm);
    prep_aeps_kernel<<<N_SAMPLES / 8, 256>>>(A);
    phase1_kernel<<<64 * NSLICE, THREADS, SMEM_WORDS * 4>>>(A);
    combine_kernel<<<N_SAMPLES / 256, 256>>>();
    rescue_kernel<<<2048, 256, (RS_AW + 2 * RS_BW) * 4>>>(A, Bm);
    gather_kernel<<<N_SAMPLES / 8, 256>>>(A, Bm, out);
}

// round 17
// speedup vs baseline: 1.3957x; 1.2459x over previous
#include <cuda_runtime.h>
#include <float.h>
#include <stdint.h>

#define DIM 128
#define N_SAMPLES 8192
#define N_EMBED 10000
#define N_EMBED_PAD 10240
#define TM 128
#define TN 64
#define THREADS 256
#define NSLICE 16
#define SLICE_W 640
#define NCH 10

typedef unsigned long long u64;

__device__ float    g_cnorm[N_EMBED_PAD];
__device__ u64      g_best[N_SAMPLES];
__device__ __align__(256) uint32_t g_bT[N_EMBED_PAD * (DIM / 2)];  // fp16 [n][k] packed
__device__ __align__(256) uint32_t g_aT[64 * 8192];                // fp16 A frags per m-tile
__device__ __align__(256) float    g_bmT[(size_t)N_EMBED_PAD * DIM]; // fp32 [j][k]
__device__ u64      g_t1[NSLICE * N_SAMPLES];
__device__ float    g_t2[NSLICE * N_SAMPLES];
__device__ float    g_eps[N_SAMPLES];
__device__ unsigned g_maxbhi, g_maxblo;
__device__ int      g_rescue_count;
__device__ int      g_rescue_list[N_SAMPLES];

__device__ __forceinline__ unsigned smem_u32(const void* p) {
    return (unsigned)__cvta_generic_to_shared(p);
}
__device__ __forceinline__ void cp16(unsigned dst, const void* src) {
    asm volatile("cp.async.cg.shared.global [%0], [%1], 16;" :: "r"(dst), "l"(src));
}
__device__ __forceinline__ void cp16z(unsigned dst, const void* src, int sz) {
    asm volatile("cp.async.cg.shared.global [%0], [%1], 16, %2;"
                 :: "r"(dst), "l"(src), "r"(sz));
}
__device__ __forceinline__ u64 enc_best(float v, int j) {
    unsigned b = __float_as_uint(v);
    b = ((int)b < 0) ? ~b : (b | 0x80000000u);
    return ((u64)b << 32) | (unsigned)(~j);
}
__device__ __forceinline__ float dec_val(u64 p) {
    unsigned b = (unsigned)(p >> 32);
    unsigned f = (b & 0x80000000u) ? (b ^ 0x80000000u) : ~b;
    return __uint_as_float(f);
}
__device__ __forceinline__ float f16rt(float v, float* lo) {
    unsigned short hb; float hf;
    asm("cvt.rn.f16.f32 %0, %1;" : "=h"(hb) : "f"(v));
    asm("cvt.f32.f16 %0, %1;"    : "=f"(hf) : "h"(hb));
    *lo = v - hf;
    return hf;
}
__device__ __forceinline__ unsigned short f16of(float v) {
    unsigned short hb;
    asm("cvt.rn.f16.f32 %0, %1;" : "=h"(hb) : "f"(v));
    return hb;
}
__device__ __forceinline__ void hsplit2hi(float x, float y, uint32_t& hw) {
    hw = (uint32_t)f16of(x) | ((uint32_t)f16of(y) << 16);
}
__device__ __forceinline__ void mma_f16(float* d, uint4 a, uint32_t b0, uint32_t b1) {
    asm volatile(
        "mma.sync.aligned.m16n8k16.row.col.f32.f16.f16.f32 "
        "{%0,%1,%2,%3}, {%4,%5,%6,%7}, {%8,%9}, {%0,%1,%2,%3};"
        : "+f"(d[0]), "+f"(d[1]), "+f"(d[2]), "+f"(d[3])
        : "r"(a.x), "r"(a.y), "r"(a.z), "r"(a.w), "r"(b0), "r"(b1));
}
__device__ __forceinline__ void ldmx4(uint32_t& r0, uint32_t& r1, uint32_t& r2,
                                      uint32_t& r3, unsigned addr) {
    asm volatile("ldmatrix.sync.aligned.m8n8.x4.shared.b16 {%0,%1,%2,%3}, [%4];"
                 : "=r"(r0), "=r"(r1), "=r"(r2), "=r"(r3) : "r"(addr));
}

// ---------------- prep: cnorm + b-split norm maxes + counter reset ----------------
__global__ void cnorm_kernel(const float* __restrict__ cm) {
    __shared__ float red[3][4][64];
    __shared__ unsigned mhi, mlo;
    const int tid = threadIdx.x;
    const int jl  = tid & 63;
    const int dc  = tid >> 6;
    const int j   = blockIdx.x * 64 + jl;
    if (tid == 0) { mhi = 0; mlo = 0; }
    if (blockIdx.x == 0 && tid == 0) g_rescue_count = 0;
    __syncthreads();
    float s_cn = 0.f, s_hi = 0.f, s_lo = 0.f;
    if (j < N_EMBED) {
#pragma unroll 8
        for (int dd = 0; dd < 32; dd++) {
            float v = cm[(dc * 32 + dd) * N_EMBED + j];
            float lo, hf = f16rt(v, &lo);
            s_cn += v * v; s_hi += hf * hf; s_lo += lo * lo;
        }
    }
    red[0][dc][jl] = s_cn; red[1][dc][jl] = s_hi; red[2][dc][jl] = s_lo;
    __syncthreads();
    if (dc == 0) {
        float cn = red[0][0][jl] + red[0][1][jl] + red[0][2][jl] + red[0][3][jl];
        float hi = red[1][0][jl] + red[1][1][jl] + red[1][2][jl] + red[1][3][jl];
        float lo = red[2][0][jl] + red[2][1][jl] + red[2][2][jl] + red[2][3][jl];
        g_cnorm[j] = (j < N_EMBED) ? cn : -1e30f;
        if (j < N_EMBED) {
            atomicMax(&mhi, __float_as_uint(hi));
            atomicMax(&mlo, __float_as_uint(lo));
        }
    }
    __syncthreads();
    if (tid == 0) {
        atomicMax(&g_maxbhi, mhi);
        atomicMax(&g_maxblo, mlo);
    }
}

// Transpose cluster_mean -> g_bT (fp16 word-packed [n][k]) and g_bmT (fp32 [j][k]).
__global__ void prep_b_kernel(const float* __restrict__ cm) {
    __shared__ unsigned short t16[32][34];
    __shared__ float tf[32][33];
    const int jt = blockIdx.x, kt = blockIdx.y;
    const int tx = threadIdx.x, ty = threadIdx.y;   // (32, 8)
#pragma unroll
    for (int r = 0; r < 4; r++) {
        int k = kt * 32 + ty + r * 8;
        int j = jt * 32 + tx;
        float v = (j < N_EMBED) ? cm[k * N_EMBED + j] : 0.f;
        t16[ty + r * 8][tx] = f16of(v);
        tf[ty + r * 8][tx]  = v;
    }
    __syncthreads();
    const int tid = ty * 32 + tx;
#pragma unroll
    for (int r = 0; r < 2; r++) {
        int i  = tid + r * 256;
        int jl = i >> 4;
        int w  = i & 15;
        uint32_t word = (uint32_t)t16[2 * w][jl] | ((uint32_t)t16[2 * w + 1][jl] << 16);
        g_bT[(size_t)(jt * 32 + jl) * (DIM / 2) + kt * 16 + w] = word;
    }
    // fp32 transposed copy for coalesced gather: BmT[j][k]
#pragma unroll
    for (int r = 0; r < 4; r++) {
        int jl = ty + r * 8;
        g_bmT[(size_t)(jt * 32 + jl) * DIM + kt * 32 + tx] = tf[tx][jl];
    }
}

// A hi-split, fragment-major per 128-row m-tile (built ONCE, reused by all slices).
__global__ void prep_a_kernel(const float* __restrict__ A) {
    const int mt = blockIdx.x;
    const int m0 = mt * TM;
    const int tid = threadIdx.x;
    for (int i = tid; i < 2048; i += 256) {
        int li = i & 31;
        int ks = (i >> 5) & 7;
        int mq = i >> 8;
        int r = li >> 2, tg = li & 3;
        int row0 = m0 + mq * 16 + r;
        int c0 = ks * 16 + 2 * tg;
        const float* A0 = A + (size_t)row0 * DIM;
        const float* A1 = A0 + 8 * DIM;
        uint32_t h0, h1, h2, h3;
        hsplit2hi(-2.f * A0[c0],     -2.f * A0[c0 + 1], h0);
        hsplit2hi(-2.f * A1[c0],     -2.f * A1[c0 + 1], h1);
        hsplit2hi(-2.f * A0[c0 + 8], -2.f * A0[c0 + 9], h2);
        hsplit2hi(-2.f * A1[c0 + 8], -2.f * A1[c0 + 9], h3);
        *(uint4*)&g_aT[mt * 8192 + ((mq * 8 + ks) * 32 + li) * 4] =
            make_uint4(h0, h1, h2, h3);
    }
}

// Per-sample sound error bound.
__global__ void prep_aeps_kernel(const float* __restrict__ A) {
    const int w = threadIdx.x >> 5, lane = threadIdx.x & 31;
    const int s = blockIdx.x * 8 + w;
    float shi = 0.f, slo = 0.f;
#pragma unroll
    for (int r = 0; r < 4; r++) {
        float a = -2.f * A[s * DIM + lane + 32 * r];
        float lo, hf = f16rt(a, &lo);
        shi += hf * hf; slo += lo * lo;
    }
#pragma unroll
    for (int off = 16; off > 0; off >>= 1) {
        shi += __shfl_xor_sync(0xFFFFFFFFu, shi, off);
        slo += __shfl_xor_sync(0xFFFFFFFFu, slo, off);
    }
    if (lane == 0) {
        float MBHI = sqrtf(__uint_as_float(g_maxbhi));
        float MBLO = sqrtf(__uint_as_float(g_maxblo));
        float nlo = sqrtf(slo), nhi = sqrtf(shi);
        g_eps[s] = 2.0002f * (nlo * MBHI + nhi * MBLO + nlo * MBLO) + 0.02f;
    }
}

// ------- phase1: hi-only mma, TM=128 x TN=64, warp 32m x 32n, 3 CTAs/SM -------
#define AW     8192
#define BROW   68
#define BHALF  (TN * BROW)               // 4352 words per buffer
#define CNS_OFF (AW + 2 * BHALF)         // 16896
#define SCR_OFF (CNS_OFF + 640)          // 17536
#define SMEM_WORDS (SCR_OFF + 768)       // 18304 words = 73.2KB -> 3 CTAs/SM

__global__ __launch_bounds__(THREADS, 3)
void phase1_kernel() {
    extern __shared__ uint32_t smw[];
    uint32_t* Aw = smw;
    uint32_t* Bw = smw + AW;
    float* cns = (float*)(smw + CNS_OFF);
    u64*   mt1 = (u64*)(smw + SCR_OFF);          // [2 wn][128 rows]
    float* mt2 = (float*)(smw + SCR_OFF + 512);

    const int tid  = threadIdx.x;
    const int lane = tid & 31;
    const int sy   = tid >> 5;           // 8 warps: 4 m-groups x 2 n-groups
    const int wm   = sy & 3;
    const int wn   = sy >> 2;
    const int n0w  = wn * 32;
    const int mtg0 = wm * 2;
    const int tig  = lane & 3;

    const int mt  = blockIdx.x & 63;
    const int sl  = blockIdx.x >> 6;
    const int m0  = mt * TM;
    const int j00 = sl * SLICE_W;

    const int lm  = lane >> 3, lr = lane & 7;
    const int lrow = n0w + ((lm >> 1) & 1) * 8 + lr;
    const int lkb  = (lm & 1) * 8;
    const unsigned bbase0 = smem_u32(Bw) + lrow * (BROW * 4) + lkb * 2;
    const unsigned bbase1 = bbase0 + 16 * (BROW * 4);

    auto issueB = [&](int t) {
        const int j0 = j00 + t * TN;
        uint32_t* dst = Bw + (t & 1) * BHALF;
        for (int i = tid; i < 1024; i += THREADS) {   // 4 iters
            int r = i >> 4, s = i & 15;
            cp16(smem_u32(dst + r * BROW + s * 4),
                 g_bT + (size_t)(j0 + r) * (DIM / 2) + s * 4);
        }
        asm volatile("cp.async.commit_group;");
    };

    // A tile (full 32KB = 2048 x 16B) + cnorm slice via cp.async; they join
    // group 0 together with B chunk 0 (committed inside issueB(0)).
    {
        const uint32_t* asrc = g_aT + mt * 8192;
        for (int i = tid; i < 2048; i += THREADS)     // 8 iters
            cp16(smem_u32(Aw + i * 4), asrc + i * 4);
        if (tid < 160)
            cp16(smem_u32(cns + tid * 4), g_cnorm + j00 + tid * 4);
    }
    issueB(0);
    issueB(1);

    float b1[4], b2[4];
    int   j1[4];
#pragma unroll
    for (int i = 0; i < 4; i++) { b1[i] = -FLT_MAX; b2[i] = -FLT_MAX; j1[i] = 0; }

    for (int t = 0; t < NCH; t++) {
        if (t < NCH - 1) asm volatile("cp.async.wait_group 1;");
        else             asm volatile("cp.async.wait_group 0;");
        __syncthreads();                 // chunk t + A tile + cns resident

        const unsigned ba0 = bbase0 + (t & 1) * (BHALF * 4);
        const unsigned ba1 = bbase1 + (t & 1) * (BHALF * 4);
        const int j0 = j00 + t * TN;
        const int loff = t * TN + n0w + 2 * tig;

        float acc[2][4][4];
#pragma unroll
        for (int mq = 0; mq < 2; mq++)
#pragma unroll
            for (int nt = 0; nt < 4; nt++)
#pragma unroll
                for (int e = 0; e < 4; e++) acc[mq][nt][e] = 0.f;

        const uint32_t* ApW = Aw + (mtg0 * 8) * 128 + lane * 4;
#pragma unroll
        for (int ks = 0; ks < 8; ks++) {
            uint4 ah0 = *(const uint4*)(ApW + ks * 128);
            uint4 ah1 = *(const uint4*)(ApW + (8 + ks) * 128);
            uint32_t b00, b01, b02, b03, b10, b11, b12, b13;
            ldmx4(b00, b01, b02, b03, ba0 + ks * 32);
            ldmx4(b10, b11, b12, b13, ba1 + ks * 32);
            mma_f16(acc[0][0], ah0, b00, b01);
            mma_f16(acc[1][0], ah1, b00, b01);
            mma_f16(acc[0][1], ah0, b02, b03);
            mma_f16(acc[1][1], ah1, b02, b03);
            mma_f16(acc[0][2], ah0, b10, b11);
            mma_f16(acc[1][2], ah1, b10, b11);
            mma_f16(acc[0][3], ah0, b12, b13);
            mma_f16(acc[1][3], ah1, b12, b13);
        }

        // top-2 update with cnorm from smem (ascending j preserved).
#pragma unroll
        for (int nt = 0; nt < 4; nt++) {
            int c0 = j0 + n0w + nt * 8 + 2 * tig;
            float cn0 = cns[loff + nt * 8];
            float cn1 = cns[loff + nt * 8 + 1];
#pragma unroll
            for (int mq = 0; mq < 2; mq++) {
#pragma unroll
                for (int rb = 0; rb < 2; rb++) {
                    int st = mq * 2 + rb;
                    float v0 = acc[mq][nt][rb * 2 + 0] + cn0;
                    float v1 = acc[mq][nt][rb * 2 + 1] + cn1;
                    if (v0 > b1[st]) { b2[st] = b1[st]; b1[st] = v0; j1[st] = c0; }
                    else if (v0 > b2[st]) b2[st] = v0;
                    if (v1 > b1[st]) { b2[st] = b1[st]; b1[st] = v1; j1[st] = c0 + 1; }
                    else if (v1 > b2[st]) b2[st] = v1;
                }
            }
        }

        __syncthreads();
        if (t + 2 < NCH) issueB(t + 2);
    }

    // quad merge, stash per-wn, cross-warp merge over 2 n-groups.
#pragma unroll
    for (int s = 0; s < 4; s++) {
        float v = b1[s], v2 = b2[s];
        int   bj = j1[s];
#pragma unroll
        for (int off = 1; off < 4; off <<= 1) {
            float ov  = __shfl_xor_sync(0xFFFFFFFFu, v, off);
            int   oj  = __shfl_xor_sync(0xFFFFFFFFu, bj, off);
            float ov2 = __shfl_xor_sync(0xFFFFFFFFu, v2, off);
            float nv2 = fmaxf(fmaxf(v2, ov2), fminf(v, ov));
            if (ov > v || (ov == v && oj < bj)) { v = ov; bj = oj; }
            v2 = nv2;
        }
        if ((lane & 3) == 0) {
            int mq = s >> 1, rb = s & 1;
            int rl = (mtg0 + mq) * 16 + (lane >> 2) + rb * 8;   // 0..127
            mt1[wn * 128 + rl] = enc_best(v, bj);
            mt2[wn * 128 + rl] = v2;
        }
    }
    __syncthreads();
    if (tid < 128) {
        int r = tid;
        u64 m0v = mt1[r], m1v = mt1[128 + r];
        float s0 = mt2[r], s1 = mt2[128 + r];
        u64 m; float v2;
        if (m0v >= m1v) { m = m0v; v2 = fmaxf(s0, fmaxf(dec_val(m1v), s1)); }
        else            { m = m1v; v2 = fmaxf(s1, fmaxf(dec_val(m0v), s0)); }
        g_t1[sl * N_SAMPLES + m0 + r] = m;
        g_t2[sl * N_SAMPLES + m0 + r] = v2;
    }
}

// ---------------- combine: global top-2, gap test, rescue list ----------------
__global__ void combine_kernel() {
    const int s = blockIdx.x * 256 + threadIdx.x;
    u64 m1 = 0; int i1 = 0;
#pragma unroll
    for (int i = 0; i < NSLICE; i++) {
        u64 t = g_t1[i * N_SAMPLES + s];
        if (t > m1) { m1 = t; i1 = i; }
    }
    float v1 = dec_val(m1);
    float v2 = -FLT_MAX;
#pragma unroll
    for (int i = 0; i < NSLICE; i++) {
        float c = (i == i1) ? g_t2[i * N_SAMPLES + s]
                            : fmaxf(dec_val(g_t1[i * N_SAMPLES + s]),
                                    g_t2[i * N_SAMPLES + s]);
        v2 = fmaxf(v2, c);
    }
    if (v1 - v2 > g_eps[s]) {
        g_best[s] = m1;
    } else {
        g_best[s] = 0;
        int p = atomicAdd(&g_rescue_count, 1);
        g_rescue_list[p] = s;
    }
}

// ---------------- rescue: exact fp32 re-scan, 16-way j-sliced ----------------
#define RS_AW 4096
#define RS_BW 16384
__global__ __launch_bounds__(256)
void rescue_kernel(const float* __restrict__ A, const float* __restrict__ Bm) {
    const int cnt = *(volatile int*)&g_rescue_count;
    const int sb = blockIdx.x >> 4, sl = blockIdx.x & 15;
    if (sb * 32 >= cnt) return;
    const int nval = min(32, cnt - sb * 32);

    extern __shared__ float smf[];
    float* As = smf;
    float* Bs = smf + RS_AW;

    const int tid = threadIdx.x, lane = tid & 31, w = tid >> 5;
    const int j00 = sl * SLICE_W;

    auto issueB = [&](int t) {
        const int j0 = j00 + t * 128;
        float* dst = Bs + (t & 1) * RS_BW;
        for (int i = tid; i < 4096; i += 256) {
            int k = i >> 5, j4 = (i & 31) * 4;
            int j = j0 + j4;
            cp16z(smem_u32(dst + k * 128 + j4),
                  Bm + (size_t)k * N_EMBED + min(j, N_EMBED - 4),
                  (j < N_EMBED) ? 16 : 0);
        }
        asm volatile("cp.async.commit_group;");
    };

    issueB(0);
    issueB(1);

    for (int i = tid; i < 1024; i += 256) {
        int si = i >> 5, k4 = (i & 31) * 4;
        float4 v = make_float4(0.f, 0.f, 0.f, 0.f);
        if (si < nval) {
            int s = g_rescue_list[sb * 32 + si];
            v = *(const float4*)&A[(size_t)s * DIM + k4];
        }
        As[(k4 + 0) * 32 + si] = -2.f * v.x;
        As[(k4 + 1) * 32 + si] = -2.f * v.y;
        As[(k4 + 2) * 32 + si] = -2.f * v.z;
        As[(k4 + 3) * 32 + si] = -2.f * v.w;
    }

    float bestv[4]; int bestj[4];
#pragma unroll
    for (int i = 0; i < 4; i++) { bestv[i] = -FLT_MAX; bestj[i] = 0; }

    for (int t = 0; t < 5; t++) {
        if (t < 4) asm volatile("cp.async.wait_group 1;");
        else       asm volatile("cp.async.wait_group 0;");
        __syncthreads();
        const float* bp = Bs + (t & 1) * RS_BW;
        const int j0 = j00 + t * 128;

        float acc[4][4];
#pragma unroll
        for (int g = 0; g < 4; g++) {
            float cn = __ldg(&g_cnorm[j0 + lane + 32 * g]);
#pragma unroll
            for (int si = 0; si < 4; si++) acc[si][g] = cn;
        }
#pragma unroll 4
        for (int k = 0; k < DIM; k++) {
            float4 a4 = *(const float4*)&As[k * 32 + 4 * w];
            float a[4] = {a4.x, a4.y, a4.z, a4.w};
#pragma unroll
            for (int g = 0; g < 4; g++) {
                float b = bp[k * 128 + lane + 32 * g];
#pragma unroll
                for (int si = 0; si < 4; si++) acc[si][g] = fmaf(a[si], b, acc[si][g]);
            }
        }
#pragma unroll
        for (int g = 0; g < 4; g++) {
            int j = j0 + lane + 32 * g;
#pragma unroll
            for (int si = 0; si < 4; si++) {
                if (acc[si][g] > bestv[si]) { bestv[si] = acc[si][g]; bestj[si] = j; }
            }
        }
        __syncthreads();
        if (t + 2 < 5) issueB(t + 2);
    }

#pragma unroll
    for (int si = 0; si < 4; si++) {
        float v = bestv[si]; int bj = bestj[si];
#pragma unroll
        for (int off = 16; off > 0; off >>= 1) {
            float ov = __shfl_xor_sync(0xFFFFFFFFu, v, off);
            int   oj = __shfl_xor_sync(0xFFFFFFFFu, bj, off);
            if (ov > v || (ov == v && oj < bj)) { v = ov; bj = oj; }
        }
        int gi = 4 * w + si;
        if (lane == 0 && gi < nval)
            atomicMax(&g_best[g_rescue_list[sb * 32 + gi]], enc_best(v, bj));
    }
}

// ---------------- gather: coalesced via BmT ----------------
__global__ void gather_kernel(const float* __restrict__ A,
                              float* __restrict__ out) {
    const int w = threadIdx.x >> 5, lane = threadIdx.x & 31;
    const int s = blockIdx.x * 8 + w;
    const int j = (int)(unsigned)(~(unsigned)g_best[s]);
    float sum = 0.f;
#pragma unroll
    for (int r = 0; r < 4; r++) {
        const int d = lane + r * 32;
        float q = g_bmT[(size_t)j * DIM + d];
        out[s * DIM + d] = q;
        float x = A[s * DIM + d];
        float t = x - q;
        sum += t * t;
    }
#pragma unroll
    for (int off = 16; off > 0; off >>= 1)
        sum += __shfl_xor_sync(0xFFFFFFFFu, sum, off);
    if (lane == 0) {
        out[N_SAMPLES * DIM + s] = (float)j;
        out[N_SAMPLES * (DIM + 1) + s] = sum * (1.0f / DIM);
    }
}

extern "C" void kernel_launch(void* const* d_in, const int* in_sizes, int n_in,
                              void* d_out, int out_size) {
    const float* A  = (const float*)d_in[0];
    const float* Bm = (const float*)d_in[1];
    if (n_in >= 2 && in_sizes[0] == DIM * N_EMBED) {
        const float* t = A; A = Bm; Bm = t;
    }
    float* out = (float*)d_out;

    static int attr_set = 0;
    if (!attr_set) {
        cudaFuncSetAttribute(phase1_kernel,
            cudaFuncAttributeMaxDynamicSharedMemorySize, SMEM_WORDS * 4);
        cudaFuncSetAttribute(rescue_kernel,
            cudaFuncAttributeMaxDynamicSharedMemorySize, (RS_AW + 2 * RS_BW) * 4);
        attr_set = 1;
    }

    cnorm_kernel<<<N_EMBED_PAD / 64, 256>>>(Bm);
    dim3 gB(N_EMBED_PAD / 32, DIM / 32), bB(32, 8);
    prep_b_kernel<<<gB, bB>>>(Bm);
    prep_a_kernel<<<64, 256>>>(A);
    prep_aeps_kernel<<<N_SAMPLES / 8, 256>>>(A);
    phase1_kernel<<<64 * NSLICE, THREADS, SMEM_WORDS * 4>>>();
    combine_kernel<<<N_SAMPLES / 256, 256>>>();
    rescue_kernel<<<4096, 256, (RS_AW + 2 * RS_BW) * 4>>>(A, Bm);
    gather_kernel<<<N_SAMPLES / 8, 256>>>(A, out);
}